// round 1
// baseline (speedup 1.0000x reference)
#include <cuda_runtime.h>
#include <math.h>

#define BB 2
#define TT 2048
#define DD 2048
#define HH 16
#define KVH 4
#define HD 128
#define RD 64

// ---------------- device scratch (no allocs allowed) ----------------
__device__ float g_qs[4096 * 2048];   // Q = x@Wq, [B*T, H*HD], roped in place
__device__ float g_ks[4096 * 512];    // K = x@Wk, [B*T, KV*HD] (pre-rope)
__device__ float g_vs[4096 * 512];    // V = x@Wv
__device__ float g_att[4096 * 2048];  // attention out, [B*T, H*HD]

// ---------------- SGEMM: C[M,N] = A[M,K] @ B[K,N], all row-major -----
// 128x128 tile, BK=16, 256 threads, 8x8 per thread. Dims assumed %128/%16.
__global__ __launch_bounds__(256) void sgemm128(
    const float* __restrict__ A, const float* __restrict__ B,
    float* __restrict__ C, int M, int N, int K) {
    __shared__ float As[16][128];
    __shared__ float Bs[16][128];
    int tid = threadIdx.x;
    int brow = blockIdx.y * 128, bcol = blockIdx.x * 128;
    int trow = (tid >> 4) * 8, tcol = (tid & 15) * 8;

    int arow = tid >> 2;            // 0..63
    int akc  = (tid & 3) * 4;       // 0,4,8,12
    int bkr  = tid >> 5;            // 0..7
    int bc4  = (tid & 31) * 4;      // 0..124

    const float* Ap  = A + (size_t)(brow + arow) * K + akc;
    const float* Ap2 = Ap + (size_t)64 * K;
    const float* Bp  = B + (size_t)bkr * N + bcol + bc4;
    const float* Bp2 = Bp + (size_t)8 * N;

    float acc[8][8];
    #pragma unroll
    for (int i = 0; i < 8; i++)
        #pragma unroll
        for (int j = 0; j < 8; j++) acc[i][j] = 0.f;

    for (int k0 = 0; k0 < K; k0 += 16) {
        float4 a1 = *(const float4*)(Ap + k0);
        float4 a2 = *(const float4*)(Ap2 + k0);
        float4 b1 = *(const float4*)(Bp + (size_t)k0 * N);
        float4 b2 = *(const float4*)(Bp2 + (size_t)k0 * N);
        __syncthreads();
        As[akc + 0][arow] = a1.x; As[akc + 1][arow] = a1.y;
        As[akc + 2][arow] = a1.z; As[akc + 3][arow] = a1.w;
        As[akc + 0][arow + 64] = a2.x; As[akc + 1][arow + 64] = a2.y;
        As[akc + 2][arow + 64] = a2.z; As[akc + 3][arow + 64] = a2.w;
        *(float4*)&Bs[bkr][bc4]     = b1;
        *(float4*)&Bs[bkr + 8][bc4] = b2;
        __syncthreads();
        #pragma unroll
        for (int k = 0; k < 16; k++) {
            float4 a01 = *(const float4*)&As[k][trow];
            float4 a23 = *(const float4*)&As[k][trow + 4];
            float4 b01 = *(const float4*)&Bs[k][tcol];
            float4 b23 = *(const float4*)&Bs[k][tcol + 4];
            float av[8] = {a01.x, a01.y, a01.z, a01.w, a23.x, a23.y, a23.z, a23.w};
            float bv[8] = {b01.x, b01.y, b01.z, b01.w, b23.x, b23.y, b23.z, b23.w};
            #pragma unroll
            for (int i = 0; i < 8; i++)
                #pragma unroll
                for (int j = 0; j < 8; j++) acc[i][j] += av[i] * bv[j];
        }
    }
    float* Cp = C + (size_t)(brow + trow) * N + bcol + tcol;
    #pragma unroll
    for (int i = 0; i < 8; i++) {
        float4 c0 = make_float4(acc[i][0], acc[i][1], acc[i][2], acc[i][3]);
        float4 c1 = make_float4(acc[i][4], acc[i][5], acc[i][6], acc[i][7]);
        *(float4*)(Cp + (size_t)i * N) = c0;
        *(float4*)(Cp + (size_t)i * N + 4) = c1;
    }
}

// ---------------- RoPE on Q, in place --------------------------------
// grid = B*T*H blocks of 128 threads; block handles one head-row.
__global__ void rope_q_kernel(float* __restrict__ qs,
                              const float* __restrict__ fcos,
                              const float* __restrict__ fsin) {
    __shared__ float sh[HD];
    int d = threadIdx.x;
    size_t base = (size_t)blockIdx.x * HD;
    int t = (blockIdx.x / HH) % TT;
    float val = qs[base + d];
    sh[d] = val;
    __syncthreads();
    if (d < RD) {
        int i = d >> 1;
        float c = fcos[t * (RD / 2) + i];
        float s = fsin[t * (RD / 2) + i];
        float out = (d & 1) ? (sh[d - 1] * s + val * c)
                            : (val * c - sh[d + 1] * s);
        qs[base + d] = out;
    }
}

// ------- RoPE on K + transpose K,V into present layout [B,KV,T,HD] ---
// grid = B*T*KV blocks of 128 threads.
__global__ void rope_kv_kernel(const float* __restrict__ ks,
                               const float* __restrict__ vs,
                               const float* __restrict__ fcos,
                               const float* __restrict__ fsin,
                               float* __restrict__ outK,
                               float* __restrict__ outV) {
    __shared__ float sh[HD];
    int d = threadIdx.x;
    size_t base = (size_t)blockIdx.x * HD;
    int kv = blockIdx.x % KVH;
    int t  = (blockIdx.x / KVH) % TT;
    int b  = blockIdx.x / (KVH * TT);
    float val = ks[base + d];
    sh[d] = val;
    __syncthreads();
    float out = val;
    if (d < RD) {
        int i = d >> 1;
        float c = fcos[t * (RD / 2) + i];
        float s = fsin[t * (RD / 2) + i];
        out = (d & 1) ? (sh[d - 1] * s + val * c)
                      : (val * c - sh[d + 1] * s);
    }
    size_t dst = ((size_t)(b * KVH + kv) * TT + t) * HD + d;
    outK[dst] = out;
    outV[dst] = vs[base + d];
}

// ---------------- causal flash attention ------------------------------
// grid (T/32, H, B), 128 threads. Q: [B*T, H*HD]; K,V: [B,KV,T,HD];
// O: [B*T, H*HD]. Warp w owns q rows q0+8w..q0+8w+7; lane owns kv col.
__global__ __launch_bounds__(128) void flash_kernel(
    const float* __restrict__ Q, const float* __restrict__ K,
    const float* __restrict__ V, float* __restrict__ O) {
    __shared__ float Qs[32 * 128];
    __shared__ float sbuf[4224];   // K phase: [d][j] stride 33; V: [j][d] stride 132
    int tid = threadIdx.x, lane = tid & 31, w = tid >> 5;
    int b = blockIdx.z, h = blockIdx.y, q0 = blockIdx.x * 32;
    int kvh = h >> 2;  // H/KV = 4
    const float scale = 0.08838834764831845f;  // 1/sqrt(128)

    const float* qb = Q + ((size_t)(b * TT + q0)) * (HH * HD) + h * HD;
    #pragma unroll 4
    for (int qi = 0; qi < 32; qi++)
        Qs[qi * 128 + tid] = qb[(size_t)qi * (HH * HD) + tid] * scale;

    float m[8], l[8], o[8][4];
    #pragma unroll
    for (int r = 0; r < 8; r++) {
        m[r] = -1e30f; l[r] = 0.f;
        o[r][0] = o[r][1] = o[r][2] = o[r][3] = 0.f;
    }
    int qrow0 = q0 + w * 8;
    int ntiles = q0 / 32 + 1;

    for (int tile = 0; tile < ntiles; tile++) {
        int kv0 = tile * 32;
        const float* kb = K + ((size_t)(b * KVH + kvh) * TT + kv0) * HD;
        __syncthreads();
        #pragma unroll 4
        for (int j = 0; j < 32; j++)
            sbuf[tid * 33 + j] = kb[(size_t)j * HD + tid];
        __syncthreads();

        float s[8];
        #pragma unroll
        for (int r = 0; r < 8; r++) s[r] = 0.f;
        const float* qrow = &Qs[w * 8 * 128];
        #pragma unroll 4
        for (int k = 0; k < 128; k++) {
            float kt = sbuf[k * 33 + lane];
            #pragma unroll
            for (int r = 0; r < 8; r++) s[r] += qrow[r * 128 + k] * kt;
        }
        int kvidx = kv0 + lane;
        float p[8];
        #pragma unroll
        for (int r = 0; r < 8; r++) {
            if (kvidx > qrow0 + r) s[r] = -1e30f;
            float mt = s[r];
            #pragma unroll
            for (int off = 16; off > 0; off >>= 1)
                mt = fmaxf(mt, __shfl_xor_sync(0xffffffffu, mt, off));
            float mn = fmaxf(m[r], mt);
            float sc = __expf(m[r] - mn);
            float pr = __expf(s[r] - mn);
            float ps = pr;
            #pragma unroll
            for (int off = 16; off > 0; off >>= 1)
                ps += __shfl_xor_sync(0xffffffffu, ps, off);
            l[r] = l[r] * sc + ps;
            m[r] = mn;
            o[r][0] *= sc; o[r][1] *= sc; o[r][2] *= sc; o[r][3] *= sc;
            p[r] = pr;
        }

        const float* vb = V + ((size_t)(b * KVH + kvh) * TT + kv0) * HD;
        __syncthreads();
        #pragma unroll 4
        for (int j = 0; j < 32; j++)
            sbuf[j * 132 + tid] = vb[(size_t)j * HD + tid];
        __syncthreads();

        #pragma unroll 4
        for (int j = 0; j < 32; j++) {
            float v0 = sbuf[j * 132 + lane];
            float v1 = sbuf[j * 132 + lane + 32];
            float v2 = sbuf[j * 132 + lane + 64];
            float v3 = sbuf[j * 132 + lane + 96];
            #pragma unroll
            for (int r = 0; r < 8; r++) {
                float pj = __shfl_sync(0xffffffffu, p[r], j);
                o[r][0] += pj * v0; o[r][1] += pj * v1;
                o[r][2] += pj * v2; o[r][3] += pj * v3;
            }
        }
    }

    float* ob = O + ((size_t)(b * TT + qrow0)) * (HH * HD) + h * HD;
    #pragma unroll
    for (int r = 0; r < 8; r++) {
        float inv = 1.f / l[r];
        ob[(size_t)r * (HH * HD) + lane]      = o[r][0] * inv;
        ob[(size_t)r * (HH * HD) + lane + 32] = o[r][1] * inv;
        ob[(size_t)r * (HH * HD) + lane + 64] = o[r][2] * inv;
        ob[(size_t)r * (HH * HD) + lane + 96] = o[r][3] * inv;
    }
}

// ---------------- launch --------------------------------------------
extern "C" void kernel_launch(void* const* d_in, const int* in_sizes, int n_in,
                              void* d_out, int out_size) {
    const float* x    = (const float*)d_in[0];
    const float* fcos = (const float*)d_in[1];
    const float* fsin = (const float*)d_in[2];
    const float* Wq   = (const float*)d_in[3];
    const float* Wk   = (const float*)d_in[4];
    const float* Wv   = (const float*)d_in[5];
    const float* Wo   = (const float*)d_in[6];

    float* y    = (float*)d_out;                              // [B,T,D]
    float* outK = y + (size_t)BB * TT * DD;                   // [B,KV,T,HD]
    float* outV = outK + (size_t)BB * KVH * TT * HD;          // [B,KV,T,HD]

    float *qs, *ks, *vs, *att;
    cudaGetSymbolAddress((void**)&qs,  g_qs);
    cudaGetSymbolAddress((void**)&ks,  g_ks);
    cudaGetSymbolAddress((void**)&vs,  g_vs);
    cudaGetSymbolAddress((void**)&att, g_att);

    const int M = BB * TT;  // 4096

    sgemm128<<<dim3(DD / 128, M / 128), 256>>>(x, Wq, qs, M, HH * HD, DD);
    sgemm128<<<dim3((KVH * HD) / 128, M / 128), 256>>>(x, Wk, ks, M, KVH * HD, DD);
    sgemm128<<<dim3((KVH * HD) / 128, M / 128), 256>>>(x, Wv, vs, M, KVH * HD, DD);

    rope_q_kernel<<<M * HH, 128>>>(qs, fcos, fsin);
    rope_kv_kernel<<<M * KVH, 128>>>(ks, vs, fcos, fsin, outK, outV);

    flash_kernel<<<dim3(TT / 32, HH, BB), 128>>>(qs, outK, outV, att);

    sgemm128<<<dim3(DD / 128, M / 128), 256>>>(att, Wo, y, M, DD, DD);
}

// round 2
// speedup vs baseline: 1.4337x; 1.4337x over previous
#include <cuda_runtime.h>
#include <math.h>
#include <stdint.h>

#define BB 2
#define TT 2048
#define DD 2048
#define HH 16
#define KVH 4
#define HD 128
#define RD 64

// ---------------- device scratch (no allocs allowed) ----------------
__device__ float g_qs[4096 * 2048];   // Q = x@Wq, [B*T, H*HD], roped in place
__device__ float g_ks[4096 * 512];    // K = x@Wk, [B*T, KV*HD] (pre-rope)
__device__ float g_vs[4096 * 512];    // V = x@Wv
__device__ float g_att[4096 * 2048];  // attention out, [B*T, H*HD]

__device__ __forceinline__ uint32_t f2tf(float x) {
    uint32_t r;
    asm("cvt.rna.tf32.f32 %0, %1;" : "=r"(r) : "f"(x));
    return r;
}

// -------- TF32 tensor-core GEMM: C[M,N] = A[M,K] @ B[K,N], row-major --
// 128x128 tile, BK=16, 256 threads = 8 warps, warp tile 64x32 via
// mma.sync.m16n8k8.tf32. Dims assumed %128 (N) / %16 (K) / %128 (M).
#define SAS 136  // smem row stride (floats): conflict-free for frags & STS

__global__ __launch_bounds__(256) void gemm_tf32(
    const float* __restrict__ A, const float* __restrict__ B,
    float* __restrict__ C, int M, int N, int K) {
    __shared__ float As[16 * SAS];  // [k][m]
    __shared__ float Bs[16 * SAS];  // [k][n]
    int tid = threadIdx.x, lane = tid & 31;
    int w = tid >> 5, wm = w & 1, wn = w >> 1;     // 2x4 warp grid
    int m0 = wm * 64, n0 = wn * 32;
    int g = lane >> 2, tig = lane & 3;
    int brow = blockIdx.y * 128, bcol = blockIdx.x * 128;

    // G2S: A — each thread loads rows (arow, arow+64), k-cols akc..akc+3
    int arow = tid & 63, akc = (tid >> 6) * 4;
    // G2S: B — rows bkr, bkr+8; 4 consecutive n-cols
    int bkr = tid >> 5, bc4 = (tid & 31) * 4;

    const float* Ap  = A + (size_t)(brow + arow) * K + akc;
    const float* Ap2 = Ap + (size_t)64 * K;
    const float* Bp  = B + (size_t)bkr * N + bcol + bc4;
    const float* Bp2 = Bp + (size_t)8 * N;

    float acc[4][4][4];
    #pragma unroll
    for (int mt = 0; mt < 4; mt++)
        #pragma unroll
        for (int nt = 0; nt < 4; nt++)
            #pragma unroll
            for (int i = 0; i < 4; i++) acc[mt][nt][i] = 0.f;

    for (int k0 = 0; k0 < K; k0 += 16) {
        float4 a1 = *(const float4*)(Ap + k0);
        float4 a2 = *(const float4*)(Ap2 + k0);
        float4 b1 = *(const float4*)(Bp + (size_t)k0 * N);
        float4 b2 = *(const float4*)(Bp2 + (size_t)k0 * N);
        __syncthreads();
        As[(akc + 0) * SAS + arow] = a1.x;
        As[(akc + 1) * SAS + arow] = a1.y;
        As[(akc + 2) * SAS + arow] = a1.z;
        As[(akc + 3) * SAS + arow] = a1.w;
        As[(akc + 0) * SAS + arow + 64] = a2.x;
        As[(akc + 1) * SAS + arow + 64] = a2.y;
        As[(akc + 2) * SAS + arow + 64] = a2.z;
        As[(akc + 3) * SAS + arow + 64] = a2.w;
        *(float4*)&Bs[bkr * SAS + bc4]       = b1;
        *(float4*)&Bs[(bkr + 8) * SAS + bc4] = b2;
        __syncthreads();

        #pragma unroll
        for (int ks = 0; ks < 16; ks += 8) {
            uint32_t af[4][4], bf[4][2];
            #pragma unroll
            for (int mt = 0; mt < 4; mt++) {
                int rm = m0 + mt * 16;
                af[mt][0] = f2tf(As[(ks + tig)     * SAS + rm + g]);
                af[mt][1] = f2tf(As[(ks + tig)     * SAS + rm + g + 8]);
                af[mt][2] = f2tf(As[(ks + tig + 4) * SAS + rm + g]);
                af[mt][3] = f2tf(As[(ks + tig + 4) * SAS + rm + g + 8]);
            }
            #pragma unroll
            for (int nt = 0; nt < 4; nt++) {
                int cn = n0 + nt * 8;
                bf[nt][0] = f2tf(Bs[(ks + tig)     * SAS + cn + g]);
                bf[nt][1] = f2tf(Bs[(ks + tig + 4) * SAS + cn + g]);
            }
            #pragma unroll
            for (int mt = 0; mt < 4; mt++)
                #pragma unroll
                for (int nt = 0; nt < 4; nt++)
                    asm volatile(
                        "mma.sync.aligned.m16n8k8.row.col.f32.tf32.tf32.f32 "
                        "{%0,%1,%2,%3}, {%4,%5,%6,%7}, {%8,%9}, {%0,%1,%2,%3};"
                        : "+f"(acc[mt][nt][0]), "+f"(acc[mt][nt][1]),
                          "+f"(acc[mt][nt][2]), "+f"(acc[mt][nt][3])
                        : "r"(af[mt][0]), "r"(af[mt][1]),
                          "r"(af[mt][2]), "r"(af[mt][3]),
                          "r"(bf[nt][0]), "r"(bf[nt][1]));
        }
    }

    #pragma unroll
    for (int mt = 0; mt < 4; mt++) {
        int row = brow + m0 + mt * 16 + g;
        #pragma unroll
        for (int nt = 0; nt < 4; nt++) {
            int col = bcol + n0 + nt * 8 + tig * 2;
            *(float2*)&C[(size_t)row * N + col] =
                make_float2(acc[mt][nt][0], acc[mt][nt][1]);
            *(float2*)&C[(size_t)(row + 8) * N + col] =
                make_float2(acc[mt][nt][2], acc[mt][nt][3]);
        }
    }
}

// ---------------- RoPE on Q, in place --------------------------------
__global__ void rope_q_kernel(float* __restrict__ qs,
                              const float* __restrict__ fcos,
                              const float* __restrict__ fsin) {
    __shared__ float sh[HD];
    int d = threadIdx.x;
    size_t base = (size_t)blockIdx.x * HD;
    int t = (blockIdx.x / HH) % TT;
    float val = qs[base + d];
    sh[d] = val;
    __syncthreads();
    if (d < RD) {
        int i = d >> 1;
        float c = fcos[t * (RD / 2) + i];
        float s = fsin[t * (RD / 2) + i];
        float out = (d & 1) ? (sh[d - 1] * s + val * c)
                            : (val * c - sh[d + 1] * s);
        qs[base + d] = out;
    }
}

// ------- RoPE on K + transpose K,V into present layout [B,KV,T,HD] ---
__global__ void rope_kv_kernel(const float* __restrict__ ks,
                               const float* __restrict__ vs,
                               const float* __restrict__ fcos,
                               const float* __restrict__ fsin,
                               float* __restrict__ outK,
                               float* __restrict__ outV) {
    __shared__ float sh[HD];
    int d = threadIdx.x;
    size_t base = (size_t)blockIdx.x * HD;
    int kv = blockIdx.x % KVH;
    int t  = (blockIdx.x / KVH) % TT;
    int b  = blockIdx.x / (KVH * TT);
    float val = ks[base + d];
    sh[d] = val;
    __syncthreads();
    float out = val;
    if (d < RD) {
        int i = d >> 1;
        float c = fcos[t * (RD / 2) + i];
        float s = fsin[t * (RD / 2) + i];
        out = (d & 1) ? (sh[d - 1] * s + val * c)
                      : (val * c - sh[d + 1] * s);
    }
    size_t dst = ((size_t)(b * KVH + kv) * TT + t) * HD + d;
    outK[dst] = out;
    outV[dst] = vs[base + d];
}

// ---------------- causal flash attention ------------------------------
__global__ __launch_bounds__(128) void flash_kernel(
    const float* __restrict__ Q, const float* __restrict__ K,
    const float* __restrict__ V, float* __restrict__ O) {
    __shared__ float Qs[32 * 128];
    __shared__ float sbuf[4224];
    int tid = threadIdx.x, lane = tid & 31, w = tid >> 5;
    int b = blockIdx.z, h = blockIdx.y, q0 = blockIdx.x * 32;
    int kvh = h >> 2;
    const float scale = 0.08838834764831845f;

    const float* qb = Q + ((size_t)(b * TT + q0)) * (HH * HD) + h * HD;
    #pragma unroll 4
    for (int qi = 0; qi < 32; qi++)
        Qs[qi * 128 + tid] = qb[(size_t)qi * (HH * HD) + tid] * scale;

    float m[8], l[8], o[8][4];
    #pragma unroll
    for (int r = 0; r < 8; r++) {
        m[r] = -1e30f; l[r] = 0.f;
        o[r][0] = o[r][1] = o[r][2] = o[r][3] = 0.f;
    }
    int qrow0 = q0 + w * 8;
    int ntiles = q0 / 32 + 1;

    for (int tile = 0; tile < ntiles; tile++) {
        int kv0 = tile * 32;
        const float* kb = K + ((size_t)(b * KVH + kvh) * TT + kv0) * HD;
        __syncthreads();
        #pragma unroll 4
        for (int j = 0; j < 32; j++)
            sbuf[tid * 33 + j] = kb[(size_t)j * HD + tid];
        __syncthreads();

        float s[8];
        #pragma unroll
        for (int r = 0; r < 8; r++) s[r] = 0.f;
        const float* qrow = &Qs[w * 8 * 128];
        #pragma unroll 4
        for (int k = 0; k < 128; k++) {
            float kt = sbuf[k * 33 + lane];
            #pragma unroll
            for (int r = 0; r < 8; r++) s[r] += qrow[r * 128 + k] * kt;
        }
        int kvidx = kv0 + lane;
        float p[8];
        #pragma unroll
        for (int r = 0; r < 8; r++) {
            if (kvidx > qrow0 + r) s[r] = -1e30f;
            float mt = s[r];
            #pragma unroll
            for (int off = 16; off > 0; off >>= 1)
                mt = fmaxf(mt, __shfl_xor_sync(0xffffffffu, mt, off));
            float mn = fmaxf(m[r], mt);
            float sc = __expf(m[r] - mn);
            float pr = __expf(s[r] - mn);
            float ps = pr;
            #pragma unroll
            for (int off = 16; off > 0; off >>= 1)
                ps += __shfl_xor_sync(0xffffffffu, ps, off);
            l[r] = l[r] * sc + ps;
            m[r] = mn;
            o[r][0] *= sc; o[r][1] *= sc; o[r][2] *= sc; o[r][3] *= sc;
            p[r] = pr;
        }

        const float* vb = V + ((size_t)(b * KVH + kvh) * TT + kv0) * HD;
        __syncthreads();
        #pragma unroll 4
        for (int j = 0; j < 32; j++)
            sbuf[j * 132 + tid] = vb[(size_t)j * HD + tid];
        __syncthreads();

        #pragma unroll 4
        for (int j = 0; j < 32; j++) {
            float v0 = sbuf[j * 132 + lane];
            float v1 = sbuf[j * 132 + lane + 32];
            float v2 = sbuf[j * 132 + lane + 64];
            float v3 = sbuf[j * 132 + lane + 96];
            #pragma unroll
            for (int r = 0; r < 8; r++) {
                float pj = __shfl_sync(0xffffffffu, p[r], j);
                o[r][0] += pj * v0; o[r][1] += pj * v1;
                o[r][2] += pj * v2; o[r][3] += pj * v3;
            }
        }
    }

    float* ob = O + ((size_t)(b * TT + qrow0)) * (HH * HD) + h * HD;
    #pragma unroll
    for (int r = 0; r < 8; r++) {
        float inv = 1.f / l[r];
        ob[(size_t)r * (HH * HD) + lane]      = o[r][0] * inv;
        ob[(size_t)r * (HH * HD) + lane + 32] = o[r][1] * inv;
        ob[(size_t)r * (HH * HD) + lane + 64] = o[r][2] * inv;
        ob[(size_t)r * (HH * HD) + lane + 96] = o[r][3] * inv;
    }
}

// ---------------- launch --------------------------------------------
extern "C" void kernel_launch(void* const* d_in, const int* in_sizes, int n_in,
                              void* d_out, int out_size) {
    const float* x    = (const float*)d_in[0];
    const float* fcos = (const float*)d_in[1];
    const float* fsin = (const float*)d_in[2];
    const float* Wq   = (const float*)d_in[3];
    const float* Wk   = (const float*)d_in[4];
    const float* Wv   = (const float*)d_in[5];
    const float* Wo   = (const float*)d_in[6];

    float* y    = (float*)d_out;
    float* outK = y + (size_t)BB * TT * DD;
    float* outV = outK + (size_t)BB * KVH * TT * HD;

    float *qs, *ks, *vs, *att;
    cudaGetSymbolAddress((void**)&qs,  g_qs);
    cudaGetSymbolAddress((void**)&ks,  g_ks);
    cudaGetSymbolAddress((void**)&vs,  g_vs);
    cudaGetSymbolAddress((void**)&att, g_att);

    const int M = BB * TT;  // 4096

    gemm_tf32<<<dim3(DD / 128, M / 128), 256>>>(x, Wq, qs, M, HH * HD, DD);
    gemm_tf32<<<dim3((KVH * HD) / 128, M / 128), 256>>>(x, Wk, ks, M, KVH * HD, DD);
    gemm_tf32<<<dim3((KVH * HD) / 128, M / 128), 256>>>(x, Wv, vs, M, KVH * HD, DD);

    rope_q_kernel<<<M * HH, 128>>>(qs, fcos, fsin);
    rope_kv_kernel<<<M * KVH, 128>>>(ks, vs, fcos, fsin, outK, outV);

    flash_kernel<<<dim3(TT / 32, HH, BB), 128>>>(qs, outK, outV, att);

    gemm_tf32<<<dim3(DD / 128, M / 128), 256>>>(att, Wo, y, M, DD, DD);
}

// round 3
// speedup vs baseline: 2.3622x; 1.6476x over previous
#include <cuda_runtime.h>
#include <math.h>
#include <stdint.h>

#define BB 2
#define TT 2048
#define DD 2048
#define HH 16
#define KVH 4
#define HD 128
#define RD 64

// ---------------- device scratch (no allocs allowed) ----------------
__device__ float g_qs[4096 * 2048];   // Q = x@Wq, [B*T, H*HD], roped in place
__device__ float g_ks[4096 * 512];    // K = x@Wk, [B*T, KV*HD] (pre-rope)
__device__ float g_vs[4096 * 512];    // V = x@Wv
__device__ float g_att[4096 * 2048];  // attention out, [B*T, H*HD]

__device__ __forceinline__ uint32_t f2tf(float x) {
    uint32_t r;
    asm("cvt.rna.tf32.f32 %0, %1;" : "=r"(r) : "f"(x));
    return r;
}
__device__ __forceinline__ float tfs(float x) {  // tf32 bits stored as float
    uint32_t r = f2tf(x);
    return __uint_as_float(r);
}
__device__ __forceinline__ uint32_t u(float x) { return __float_as_uint(x); }

#define MMA_TF32(d0,d1,d2,d3,a0,a1,a2,a3,b0,b1)                         \
    asm volatile(                                                        \
        "mma.sync.aligned.m16n8k8.row.col.f32.tf32.tf32.f32 "           \
        "{%0,%1,%2,%3}, {%4,%5,%6,%7}, {%8,%9}, {%0,%1,%2,%3};"         \
        : "+f"(d0), "+f"(d1), "+f"(d2), "+f"(d3)                         \
        : "r"(a0), "r"(a1), "r"(a2), "r"(a3), "r"(b0), "r"(b1))

// -------- TF32 tensor-core GEMM: C[M,N] = A[M,K] @ B[K,N], row-major --
// 128x128 tile, BK=16, 256 threads = 8 warps, warp tile 64x32.
// Data converted to tf32 at the G2S store (cvt once per element).
#define SAS 136

__global__ __launch_bounds__(256) void gemm_tf32(
    const float* __restrict__ A, const float* __restrict__ B,
    float* __restrict__ C, int M, int N, int K) {
    __shared__ float As[16 * SAS];  // [k][m], tf32 bits
    __shared__ float Bs[16 * SAS];  // [k][n], tf32 bits
    int tid = threadIdx.x, lane = tid & 31;
    int w = tid >> 5, wm = w & 1, wn = w >> 1;
    int m0 = wm * 64, n0 = wn * 32;
    int g = lane >> 2, tig = lane & 3;
    int brow = blockIdx.y * 128, bcol = blockIdx.x * 128;

    int arow = tid & 63, akc = (tid >> 6) * 4;
    int bkr = tid >> 5, bc4 = (tid & 31) * 4;

    const float* Ap  = A + (size_t)(brow + arow) * K + akc;
    const float* Ap2 = Ap + (size_t)64 * K;
    const float* Bp  = B + (size_t)bkr * N + bcol + bc4;
    const float* Bp2 = Bp + (size_t)8 * N;

    float acc[4][4][4];
    #pragma unroll
    for (int mt = 0; mt < 4; mt++)
        #pragma unroll
        for (int nt = 0; nt < 4; nt++)
            #pragma unroll
            for (int i = 0; i < 4; i++) acc[mt][nt][i] = 0.f;

    for (int k0 = 0; k0 < K; k0 += 16) {
        float4 a1 = *(const float4*)(Ap + k0);
        float4 a2 = *(const float4*)(Ap2 + k0);
        float4 b1 = *(const float4*)(Bp + (size_t)k0 * N);
        float4 b2 = *(const float4*)(Bp2 + (size_t)k0 * N);
        __syncthreads();
        As[(akc + 0) * SAS + arow] = tfs(a1.x);
        As[(akc + 1) * SAS + arow] = tfs(a1.y);
        As[(akc + 2) * SAS + arow] = tfs(a1.z);
        As[(akc + 3) * SAS + arow] = tfs(a1.w);
        As[(akc + 0) * SAS + arow + 64] = tfs(a2.x);
        As[(akc + 1) * SAS + arow + 64] = tfs(a2.y);
        As[(akc + 2) * SAS + arow + 64] = tfs(a2.z);
        As[(akc + 3) * SAS + arow + 64] = tfs(a2.w);
        Bs[bkr * SAS + bc4 + 0] = tfs(b1.x);
        Bs[bkr * SAS + bc4 + 1] = tfs(b1.y);
        Bs[bkr * SAS + bc4 + 2] = tfs(b1.z);
        Bs[bkr * SAS + bc4 + 3] = tfs(b1.w);
        Bs[(bkr + 8) * SAS + bc4 + 0] = tfs(b2.x);
        Bs[(bkr + 8) * SAS + bc4 + 1] = tfs(b2.y);
        Bs[(bkr + 8) * SAS + bc4 + 2] = tfs(b2.z);
        Bs[(bkr + 8) * SAS + bc4 + 3] = tfs(b2.w);
        __syncthreads();

        #pragma unroll
        for (int ks = 0; ks < 16; ks += 8) {
            uint32_t af[4][4], bf[4][2];
            #pragma unroll
            for (int mt = 0; mt < 4; mt++) {
                int rm = m0 + mt * 16;
                af[mt][0] = u(As[(ks + tig)     * SAS + rm + g]);
                af[mt][1] = u(As[(ks + tig)     * SAS + rm + g + 8]);
                af[mt][2] = u(As[(ks + tig + 4) * SAS + rm + g]);
                af[mt][3] = u(As[(ks + tig + 4) * SAS + rm + g + 8]);
            }
            #pragma unroll
            for (int nt = 0; nt < 4; nt++) {
                int cn = n0 + nt * 8;
                bf[nt][0] = u(Bs[(ks + tig)     * SAS + cn + g]);
                bf[nt][1] = u(Bs[(ks + tig + 4) * SAS + cn + g]);
            }
            #pragma unroll
            for (int mt = 0; mt < 4; mt++)
                #pragma unroll
                for (int nt = 0; nt < 4; nt++)
                    MMA_TF32(acc[mt][nt][0], acc[mt][nt][1],
                             acc[mt][nt][2], acc[mt][nt][3],
                             af[mt][0], af[mt][1], af[mt][2], af[mt][3],
                             bf[nt][0], bf[nt][1]);
        }
    }

    #pragma unroll
    for (int mt = 0; mt < 4; mt++) {
        int row = brow + m0 + mt * 16 + g;
        #pragma unroll
        for (int nt = 0; nt < 4; nt++) {
            int col = bcol + n0 + nt * 8 + tig * 2;
            *(float2*)&C[(size_t)row * N + col] =
                make_float2(acc[mt][nt][0], acc[mt][nt][1]);
            *(float2*)&C[(size_t)(row + 8) * N + col] =
                make_float2(acc[mt][nt][2], acc[mt][nt][3]);
        }
    }
}

// ---------------- RoPE on Q, in place --------------------------------
__global__ void rope_q_kernel(float* __restrict__ qs,
                              const float* __restrict__ fcos,
                              const float* __restrict__ fsin) {
    __shared__ float sh[HD];
    int d = threadIdx.x;
    size_t base = (size_t)blockIdx.x * HD;
    int t = (blockIdx.x / HH) % TT;
    float val = qs[base + d];
    sh[d] = val;
    __syncthreads();
    if (d < RD) {
        int i = d >> 1;
        float c = fcos[t * (RD / 2) + i];
        float s = fsin[t * (RD / 2) + i];
        float out = (d & 1) ? (sh[d - 1] * s + val * c)
                            : (val * c - sh[d + 1] * s);
        qs[base + d] = out;
    }
}

// ------- RoPE on K + transpose K,V into present layout [B,KV,T,HD] ---
__global__ void rope_kv_kernel(const float* __restrict__ ks,
                               const float* __restrict__ vs,
                               const float* __restrict__ fcos,
                               const float* __restrict__ fsin,
                               float* __restrict__ outK,
                               float* __restrict__ outV) {
    __shared__ float sh[HD];
    int d = threadIdx.x;
    size_t base = (size_t)blockIdx.x * HD;
    int kv = blockIdx.x % KVH;
    int t  = (blockIdx.x / KVH) % TT;
    int b  = blockIdx.x / (KVH * TT);
    float val = ks[base + d];
    sh[d] = val;
    __syncthreads();
    float out = val;
    if (d < RD) {
        int i = d >> 1;
        float c = fcos[t * (RD / 2) + i];
        float s = fsin[t * (RD / 2) + i];
        out = (d & 1) ? (sh[d - 1] * s + val * c)
                      : (val * c - sh[d + 1] * s);
    }
    size_t dst = ((size_t)(b * KVH + kv) * TT + t) * HD + d;
    outK[dst] = out;
    outV[dst] = vs[base + d];
}

// ------------- tensor-core causal flash attention ---------------------
// grid (T/64, H, B), 128 threads = 4 warps. Warp w owns q rows
// q0+16w..q0+16w+15 (m16). KV tile 32. TF32 mma for QK^T and P@V.
// Smem (floats): Qs[64][132] | Ks[32][132] | Vs[32][132] | Ps[4][16*33]
#define FST 132
#define QS_OFF 0
#define KS_OFF (64 * FST)
#define VS_OFF (KS_OFF + 32 * FST)
#define PS_OFF (VS_OFF + 32 * FST)
#define FSMEM_FLOATS (PS_OFF + 4 * 16 * 33)

__global__ __launch_bounds__(128) void flash_mma_kernel(
    const float* __restrict__ Q, const float* __restrict__ K,
    const float* __restrict__ V, float* __restrict__ O) {
    extern __shared__ float fsm[];
    float* Qs = fsm + QS_OFF;
    float* Ks = fsm + KS_OFF;
    float* Vs = fsm + VS_OFF;

    int tid = threadIdx.x, lane = tid & 31, w = tid >> 5;
    int g = lane >> 2, tig = lane & 3;
    int b = blockIdx.z, h = blockIdx.y, q0 = blockIdx.x * 64;
    int kvh = h >> 2;
    const float scale = 0.08838834764831845f;  // 1/sqrt(128)

    // --- G2S Q (scaled, tf32) : 64 rows x 128 ---
    {
        int r = tid >> 2, cb = (tid & 3) * 4;
        const float* qg = Q + ((size_t)(b * TT + q0 + r)) * (HH * HD) + h * HD;
        const float* qg2 = qg + (size_t)32 * (HH * HD);
        #pragma unroll
        for (int i = 0; i < 8; i++) {
            float4 v = *(const float4*)(qg + cb + i * 16);
            Qs[r * FST + cb + i * 16 + 0] = tfs(v.x * scale);
            Qs[r * FST + cb + i * 16 + 1] = tfs(v.y * scale);
            Qs[r * FST + cb + i * 16 + 2] = tfs(v.z * scale);
            Qs[r * FST + cb + i * 16 + 3] = tfs(v.w * scale);
            float4 v2 = *(const float4*)(qg2 + cb + i * 16);
            Qs[(r + 32) * FST + cb + i * 16 + 0] = tfs(v2.x * scale);
            Qs[(r + 32) * FST + cb + i * 16 + 1] = tfs(v2.y * scale);
            Qs[(r + 32) * FST + cb + i * 16 + 2] = tfs(v2.z * scale);
            Qs[(r + 32) * FST + cb + i * 16 + 3] = tfs(v2.w * scale);
        }
    }
    __syncthreads();

    // --- preload Q fragments into registers ---
    uint32_t qf[16][4];
    int qw = w * 16;  // local row base
    #pragma unroll
    for (int kf = 0; kf < 16; kf++) {
        qf[kf][0] = u(Qs[(qw + g)     * FST + kf * 8 + tig]);
        qf[kf][1] = u(Qs[(qw + g + 8) * FST + kf * 8 + tig]);
        qf[kf][2] = u(Qs[(qw + g)     * FST + kf * 8 + tig + 4]);
        qf[kf][3] = u(Qs[(qw + g + 8) * FST + kf * 8 + tig + 4]);
    }

    float o[16][4];
    #pragma unroll
    for (int df = 0; df < 16; df++)
        o[df][0] = o[df][1] = o[df][2] = o[df][3] = 0.f;
    float m0 = -1e30f, m1 = -1e30f, l0 = 0.f, l1 = 0.f;

    int qglob = q0 + qw;           // warp's min global q row
    int ntiles = q0 / 32 + 2;
    float* Pw = fsm + PS_OFF + w * (16 * 33);

    for (int tile = 0; tile < ntiles; tile++) {
        int kv0 = tile * 32;
        // --- G2S K,V tile (tf32) ---
        __syncthreads();
        {
            int r = tid >> 2, cb = (tid & 3) * 4;
            const float* kg = K + ((size_t)(b * KVH + kvh) * TT + kv0 + r) * HD;
            const float* vg = V + ((size_t)(b * KVH + kvh) * TT + kv0 + r) * HD;
            #pragma unroll
            for (int i = 0; i < 8; i++) {
                float4 kv4 = *(const float4*)(kg + cb + i * 16);
                Ks[r * FST + cb + i * 16 + 0] = tfs(kv4.x);
                Ks[r * FST + cb + i * 16 + 1] = tfs(kv4.y);
                Ks[r * FST + cb + i * 16 + 2] = tfs(kv4.z);
                Ks[r * FST + cb + i * 16 + 3] = tfs(kv4.w);
                float4 vv4 = *(const float4*)(vg + cb + i * 16);
                Vs[r * FST + cb + i * 16 + 0] = tfs(vv4.x);
                Vs[r * FST + cb + i * 16 + 1] = tfs(vv4.y);
                Vs[r * FST + cb + i * 16 + 2] = tfs(vv4.z);
                Vs[r * FST + cb + i * 16 + 3] = tfs(vv4.w);
            }
        }
        __syncthreads();

        // --- S = Q K^T (4 nfrags x 16 kfrags) ---
        float s[4][4];
        #pragma unroll
        for (int nf = 0; nf < 4; nf++) {
            s[nf][0] = s[nf][1] = s[nf][2] = s[nf][3] = 0.f;
            const float* kr = &Ks[(nf * 8 + g) * FST];
            #pragma unroll
            for (int kf = 0; kf < 16; kf++) {
                uint32_t b0 = u(kr[kf * 8 + tig]);
                uint32_t b1 = u(kr[kf * 8 + tig + 4]);
                MMA_TF32(s[nf][0], s[nf][1], s[nf][2], s[nf][3],
                         qf[kf][0], qf[kf][1], qf[kf][2], qf[kf][3], b0, b1);
            }
        }

        // --- causal mask ---
        if (kv0 + 31 > qglob) {
            int r0 = qglob + g, r1 = qglob + g + 8;
            #pragma unroll
            for (int nf = 0; nf < 4; nf++) {
                int c = kv0 + nf * 8 + tig * 2;
                if (c     > r0) s[nf][0] = -1e30f;
                if (c + 1 > r0) s[nf][1] = -1e30f;
                if (c     > r1) s[nf][2] = -1e30f;
                if (c + 1 > r1) s[nf][3] = -1e30f;
            }
        }

        // --- online softmax ---
        float mx0 = -1e30f, mx1 = -1e30f;
        #pragma unroll
        for (int nf = 0; nf < 4; nf++) {
            mx0 = fmaxf(mx0, fmaxf(s[nf][0], s[nf][1]));
            mx1 = fmaxf(mx1, fmaxf(s[nf][2], s[nf][3]));
        }
        mx0 = fmaxf(mx0, __shfl_xor_sync(0xffffffffu, mx0, 1));
        mx0 = fmaxf(mx0, __shfl_xor_sync(0xffffffffu, mx0, 2));
        mx1 = fmaxf(mx1, __shfl_xor_sync(0xffffffffu, mx1, 1));
        mx1 = fmaxf(mx1, __shfl_xor_sync(0xffffffffu, mx1, 2));
        float mn0 = fmaxf(m0, mx0), mn1 = fmaxf(m1, mx1);
        float sc0 = __expf(m0 - mn0), sc1 = __expf(m1 - mn1);
        m0 = mn0; m1 = mn1;

        float ps0 = 0.f, ps1 = 0.f;
        #pragma unroll
        for (int nf = 0; nf < 4; nf++) {
            float p0 = __expf(s[nf][0] - mn0);
            float p1 = __expf(s[nf][1] - mn0);
            float p2 = __expf(s[nf][2] - mn1);
            float p3 = __expf(s[nf][3] - mn1);
            ps0 += p0 + p1; ps1 += p2 + p3;
            Pw[(g    ) * 33 + nf * 8 + tig * 2    ] = tfs(p0);
            Pw[(g    ) * 33 + nf * 8 + tig * 2 + 1] = tfs(p1);
            Pw[(g + 8) * 33 + nf * 8 + tig * 2    ] = tfs(p2);
            Pw[(g + 8) * 33 + nf * 8 + tig * 2 + 1] = tfs(p3);
        }
        ps0 += __shfl_xor_sync(0xffffffffu, ps0, 1);
        ps0 += __shfl_xor_sync(0xffffffffu, ps0, 2);
        ps1 += __shfl_xor_sync(0xffffffffu, ps1, 1);
        ps1 += __shfl_xor_sync(0xffffffffu, ps1, 2);
        l0 = l0 * sc0 + ps0;
        l1 = l1 * sc1 + ps1;

        #pragma unroll
        for (int df = 0; df < 16; df++) {
            o[df][0] *= sc0; o[df][1] *= sc0;
            o[df][2] *= sc1; o[df][3] *= sc1;
        }
        __syncwarp();

        // --- P fragments (A layout) ---
        uint32_t pa[4][4];
        #pragma unroll
        for (int kf = 0; kf < 4; kf++) {
            pa[kf][0] = u(Pw[(g    ) * 33 + kf * 8 + tig]);
            pa[kf][1] = u(Pw[(g + 8) * 33 + kf * 8 + tig]);
            pa[kf][2] = u(Pw[(g    ) * 33 + kf * 8 + tig + 4]);
            pa[kf][3] = u(Pw[(g + 8) * 33 + kf * 8 + tig + 4]);
        }
        __syncwarp();

        // --- O += P @ V ---
        #pragma unroll
        for (int df = 0; df < 16; df++) {
            #pragma unroll
            for (int kf = 0; kf < 4; kf++) {
                uint32_t b0 = u(Vs[(kf * 8 + tig)     * FST + df * 8 + g]);
                uint32_t b1 = u(Vs[(kf * 8 + tig + 4) * FST + df * 8 + g]);
                MMA_TF32(o[df][0], o[df][1], o[df][2], o[df][3],
                         pa[kf][0], pa[kf][1], pa[kf][2], pa[kf][3], b0, b1);
            }
        }
    }

    // --- epilogue ---
    float inv0 = 1.f / l0, inv1 = 1.f / l1;
    float* ob0 = O + ((size_t)(b * TT + qglob + g))     * (HH * HD) + h * HD;
    float* ob1 = O + ((size_t)(b * TT + qglob + g + 8)) * (HH * HD) + h * HD;
    #pragma unroll
    for (int df = 0; df < 16; df++) {
        int col = df * 8 + tig * 2;
        *(float2*)(ob0 + col) = make_float2(o[df][0] * inv0, o[df][1] * inv0);
        *(float2*)(ob1 + col) = make_float2(o[df][2] * inv1, o[df][3] * inv1);
    }
}

// ---------------- launch --------------------------------------------
extern "C" void kernel_launch(void* const* d_in, const int* in_sizes, int n_in,
                              void* d_out, int out_size) {
    const float* x    = (const float*)d_in[0];
    const float* fcos = (const float*)d_in[1];
    const float* fsin = (const float*)d_in[2];
    const float* Wq   = (const float*)d_in[3];
    const float* Wk   = (const float*)d_in[4];
    const float* Wv   = (const float*)d_in[5];
    const float* Wo   = (const float*)d_in[6];

    float* y    = (float*)d_out;
    float* outK = y + (size_t)BB * TT * DD;
    float* outV = outK + (size_t)BB * KVH * TT * HD;

    float *qs, *ks, *vs, *att;
    cudaGetSymbolAddress((void**)&qs,  g_qs);
    cudaGetSymbolAddress((void**)&ks,  g_ks);
    cudaGetSymbolAddress((void**)&vs,  g_vs);
    cudaGetSymbolAddress((void**)&att, g_att);

    const int M = BB * TT;  // 4096
    const int FSMEM = FSMEM_FLOATS * 4;
    static int smem_set = 0;
    if (!smem_set) {
        cudaFuncSetAttribute(flash_mma_kernel,
                             cudaFuncAttributeMaxDynamicSharedMemorySize, FSMEM);
        smem_set = 1;
    }

    gemm_tf32<<<dim3(DD / 128, M / 128), 256>>>(x, Wq, qs, M, HH * HD, DD);
    gemm_tf32<<<dim3((KVH * HD) / 128, M / 128), 256>>>(x, Wk, ks, M, KVH * HD, DD);
    gemm_tf32<<<dim3((KVH * HD) / 128, M / 128), 256>>>(x, Wv, vs, M, KVH * HD, DD);

    rope_q_kernel<<<M * HH, 128>>>(qs, fcos, fsin);
    rope_kv_kernel<<<M * KVH, 128>>>(ks, vs, fcos, fsin, outK, outV);

    flash_mma_kernel<<<dim3(TT / 64, HH, BB), 128, FSMEM>>>(qs, outK, outV, att);

    gemm_tf32<<<dim3(DD / 128, M / 128), 256>>>(att, Wo, y, M, DD, DD);
}